// round 16
// baseline (speedup 1.0000x reference)
#include <cuda_runtime.h>
#include <cuda_fp16.h>
#include <cuda_bf16.h>
#include <mma.h>
#include <math.h>
#include <stdint.h>

using namespace nvcuda;

#define NFEAT  256
#define NHID   128
#define NCLASS 40
#define Z2LD   64          // padded Z2p row stride (halves) = 128 bytes
#define MAXN   100000
#define MAXE   3200000

struct alignas(8) half4 { __half2 a, b; };

// Scratch (allocation-free: __device__ globals).
__device__ __align__(256) __half g_H0p[MAXN * NHID];   // x @ W0 (fp16)
__device__ __align__(256) __half g_H1 [MAXN * NHID];   // normalized relu hidden (fp16)
__device__ __align__(256) __half g_Z2p[MAXN * Z2LD];   // H1 @ W1 (fp16, 128B rows)
__device__ __align__(256) int    g_cnt[MAXN];          // per-dst degree histogram
__device__ __align__(256) int    g_rowstart[MAXN + 1]; // CSR row pointers
__device__ __align__(256) int    g_cursor[MAXN];       // scatter cursors
__device__ __align__(256) int2   g_edges[MAXE];        // CSR payload: {src, w bits}

// Split a float4 into packed bf16 hi (uint2) and lo (uint2).
__device__ __forceinline__ void split4(float4 v, uint2& hi, uint2& lo) {
    __nv_bfloat162 h01 = __floats2bfloat162_rn(v.x, v.y);
    __nv_bfloat162 h23 = __floats2bfloat162_rn(v.z, v.w);
    hi.x = *(uint32_t*)&h01;
    hi.y = *(uint32_t*)&h23;
    float l0 = v.x - __bfloat162float(__low2bfloat16(h01));
    float l1 = v.y - __bfloat162float(__high2bfloat16(h01));
    float l2 = v.z - __bfloat162float(__low2bfloat16(h23));
    float l3 = v.w - __bfloat162float(__high2bfloat16(h23));
    __nv_bfloat162 q01 = __floats2bfloat162_rn(l0, l1);
    __nv_bfloat162 q23 = __floats2bfloat162_rn(l2, l3);
    lo.x = *(uint32_t*)&q01;
    lo.y = *(uint32_t*)&q23;
}

// ---------------------------------------------------------------------------
// GEMM1 via WMMA split-bf16, DOUBLE-BUFFERED (unchanged).
// ---------------------------------------------------------------------------
#define G1_LDA 40
#define G1_LDB 136
#define G1_ALO   (128 * G1_LDA)
#define G1_ABUF  (2 * 128 * G1_LDA)
#define G1_BLO   (32 * G1_LDB)
#define G1_BBUF  (2 * 32 * G1_LDB)
#define G1_BBASE (2 * G1_ABUF)
#define G1_SMEM  ((2 * G1_ABUF + 2 * G1_BBUF) * 2)   // 75776 bytes

__global__ __launch_bounds__(256, 2)
void gemm1_wmma_kernel(const float* __restrict__ A, const float* __restrict__ B,
                       __half* __restrict__ C, int M)
{
    extern __shared__ __align__(16) char sm[];
    __nv_bfloat16* sb = (__nv_bfloat16*)sm;

    int tid  = threadIdx.x;
    int warp = tid >> 5;
    int lane = tid & 31;
    int wm = warp & 3;
    int wn = warp >> 2;
    int blockRow = blockIdx.x * 128;

    int aRow[4], aC4[4], bRow[4], bC4[4];
    bool aOk[4];
#pragma unroll
    for (int i = 0; i < 4; i++) {
        int idx = tid + i * 256;
        aRow[i] = idx >> 3;  aC4[i] = (idx & 7) * 4;
        aOk[i]  = (blockRow + aRow[i]) < M;
        bRow[i] = idx >> 5;  bC4[i] = (idx & 31) * 4;
    }

    wmma::fragment<wmma::accumulator, 16, 16, 16, float> acc[2][4];
#pragma unroll
    for (int i = 0; i < 2; i++)
#pragma unroll
        for (int j = 0; j < 4; j++) wmma::fill_fragment(acc[i][j], 0.0f);

    float4 pa[4], pb[4];

#pragma unroll
    for (int i = 0; i < 4; i++) {
        pa[i] = aOk[i] ? *(const float4*)(A + (size_t)(blockRow + aRow[i]) * NFEAT + aC4[i])
                       : make_float4(0.f, 0.f, 0.f, 0.f);
        pb[i] = *(const float4*)(B + (size_t)bRow[i] * NHID + bC4[i]);
    }
#pragma unroll
    for (int i = 0; i < 4; i++) {
        uint2 hi, lo;
        split4(pa[i], hi, lo);
        *(uint2*)(sb + aRow[i] * G1_LDA + aC4[i]) = hi;
        *(uint2*)(sb + G1_ALO + aRow[i] * G1_LDA + aC4[i]) = lo;
    }
#pragma unroll
    for (int i = 0; i < 4; i++) {
        uint2 hi, lo;
        split4(pb[i], hi, lo);
        *(uint2*)(sb + G1_BBASE + bRow[i] * G1_LDB + bC4[i]) = hi;
        *(uint2*)(sb + G1_BBASE + G1_BLO + bRow[i] * G1_LDB + bC4[i]) = lo;
    }
#pragma unroll
    for (int i = 0; i < 4; i++) {
        pa[i] = aOk[i] ? *(const float4*)(A + (size_t)(blockRow + aRow[i]) * NFEAT + 32 + aC4[i])
                       : make_float4(0.f, 0.f, 0.f, 0.f);
        pb[i] = *(const float4*)(B + (size_t)(32 + bRow[i]) * NHID + bC4[i]);
    }
    __syncthreads();

    for (int c = 0; c < 8; c++) {
        int cur = c & 1;
        __nv_bfloat16* abuf = sb + cur * G1_ABUF;
        __nv_bfloat16* bbuf = sb + G1_BBASE + cur * G1_BBUF;

        if (c < 7) {
            __nv_bfloat16* an = sb + (cur ^ 1) * G1_ABUF;
            __nv_bfloat16* bn = sb + G1_BBASE + (cur ^ 1) * G1_BBUF;
#pragma unroll
            for (int i = 0; i < 4; i++) {
                uint2 hi, lo;
                split4(pa[i], hi, lo);
                *(uint2*)(an + aRow[i] * G1_LDA + aC4[i]) = hi;
                *(uint2*)(an + G1_ALO + aRow[i] * G1_LDA + aC4[i]) = lo;
            }
#pragma unroll
            for (int i = 0; i < 4; i++) {
                uint2 hi, lo;
                split4(pb[i], hi, lo);
                *(uint2*)(bn + bRow[i] * G1_LDB + bC4[i]) = hi;
                *(uint2*)(bn + G1_BLO + bRow[i] * G1_LDB + bC4[i]) = lo;
            }
            if (c < 6) {
                int k0 = (c + 2) * 32;
#pragma unroll
                for (int i = 0; i < 4; i++) {
                    pa[i] = aOk[i] ? *(const float4*)(A + (size_t)(blockRow + aRow[i]) * NFEAT + k0 + aC4[i])
                                   : make_float4(0.f, 0.f, 0.f, 0.f);
                    pb[i] = *(const float4*)(B + (size_t)(k0 + bRow[i]) * NHID + bC4[i]);
                }
            }
        }

#pragma unroll
        for (int kk = 0; kk < 32; kk += 16) {
            wmma::fragment<wmma::matrix_a, 16, 16, 16, __nv_bfloat16, wmma::row_major> a_hi[2], a_lo[2];
#pragma unroll
            for (int i = 0; i < 2; i++) {
                const __nv_bfloat16* pa_ = abuf + (wm * 32 + i * 16) * G1_LDA + kk;
                wmma::load_matrix_sync(a_hi[i], pa_, G1_LDA);
                wmma::load_matrix_sync(a_lo[i], pa_ + G1_ALO, G1_LDA);
            }
#pragma unroll
            for (int j = 0; j < 4; j++) {
                wmma::fragment<wmma::matrix_b, 16, 16, 16, __nv_bfloat16, wmma::row_major> b_hi, b_lo;
                const __nv_bfloat16* pb_ = bbuf + kk * G1_LDB + wn * 64 + j * 16;
                wmma::load_matrix_sync(b_hi, pb_, G1_LDB);
                wmma::load_matrix_sync(b_lo, pb_ + G1_BLO, G1_LDB);
#pragma unroll
                for (int i = 0; i < 2; i++) {
                    wmma::mma_sync(acc[i][j], a_hi[i], b_hi, acc[i][j]);
                    wmma::mma_sync(acc[i][j], a_hi[i], b_lo, acc[i][j]);
                    wmma::mma_sync(acc[i][j], a_lo[i], b_hi, acc[i][j]);
                }
            }
        }
        __syncthreads();
    }

    float* st = (float*)sm + wm * (32 * 64);
#pragma unroll
    for (int ph = 0; ph < 2; ph++) {
        if (wn == ph) {
#pragma unroll
            for (int i = 0; i < 2; i++)
#pragma unroll
                for (int j = 0; j < 4; j++)
                    wmma::store_matrix_sync(st + (i * 16) * 64 + j * 16, acc[i][j], 64,
                                            wmma::mem_row_major);
            __syncwarp();
            int row = blockRow + wm * 32 + lane;
            if (row < M) {
                __half* dst = C + (size_t)row * NHID + wn * 64;
                const float* srow = st + lane * 64;
#pragma unroll
                for (int cc = 0; cc < 64; cc += 8) {
                    float4 f0 = *(const float4*)(srow + cc);
                    float4 f1 = *(const float4*)(srow + cc + 4);
                    uint4 o;
                    __half2 h;
                    h = __floats2half2_rn(f0.x, f0.y); o.x = *(uint32_t*)&h;
                    h = __floats2half2_rn(f0.z, f0.w); o.y = *(uint32_t*)&h;
                    h = __floats2half2_rn(f1.x, f1.y); o.z = *(uint32_t*)&h;
                    h = __floats2half2_rn(f1.z, f1.w); o.w = *(uint32_t*)&h;
                    *(uint4*)(dst + cc) = o;
                }
            }
        }
        __syncthreads();
    }
}

// ---------------------------------------------------------------------------
// CSR build step 1: histogram of destination nodes.
// ---------------------------------------------------------------------------
__global__ __launch_bounds__(256) void hist_kernel(
    const int* __restrict__ dst, int E)
{
    int e = blockIdx.x * blockDim.x + threadIdx.x;
    if (e < E) atomicAdd(&g_cnt[__ldg(dst + e)], 1);
}

// ---------------------------------------------------------------------------
// CSR build step 2: exclusive prefix sum over N counts. Single block, 1024 thr.
// Also zeroes g_cnt after its last use (replaces the memset for next call;
// g_cnt is zero-initialized at module load, so the invariant holds every call).
// ---------------------------------------------------------------------------
__global__ __launch_bounds__(1024) void scan_kernel(int N)
{
    __shared__ int s[1024];
    int t = threadIdx.x;
    int chunk = (N + 1023) / 1024;
    int beg = t * chunk;
    int end = min(beg + chunk, N);

    int sum = 0;
    for (int i = beg; i < end; i++) sum += g_cnt[i];
    s[t] = sum;
    __syncthreads();

#pragma unroll
    for (int off = 1; off < 1024; off <<= 1) {
        int v = (t >= off) ? s[t - off] : 0;
        __syncthreads();
        s[t] += v;
        __syncthreads();
    }

    int base = s[t] - sum;   // exclusive prefix
    for (int i = beg; i < end; i++) {
        g_rowstart[i] = base;
        g_cursor[i]   = base;
        base += g_cnt[i];
        g_cnt[i] = 0;        // reset for next launch (deterministic invariant)
    }
    if (t == 1023) g_rowstart[N] = s[1023];
}

// ---------------------------------------------------------------------------
// CSR build step 3: scatter (src, w) into per-dst segments.
// ---------------------------------------------------------------------------
__global__ __launch_bounds__(256) void scatter_kernel(
    const int* __restrict__ src, const int* __restrict__ dst,
    const float* __restrict__ w, int E)
{
    int e = blockIdx.x * blockDim.x + threadIdx.x;
    if (e >= E) return;
    int d = __ldg(dst + e);
    int pos = atomicAdd(&g_cursor[d], 1);
    g_edges[pos] = make_int2(__ldg(src + e), __float_as_int(__ldg(w + e)));
}

// ---------------------------------------------------------------------------
// Fused SPMM1 + bias + L2 normalize + ReLU (round-13 form, unchanged).
// ---------------------------------------------------------------------------
__global__ __launch_bounds__(256) void spmm1norm_kernel(
    const __half* __restrict__ Hin, const float* __restrict__ b0,
    __half* __restrict__ Hout, int M)
{
    int gid = blockIdx.x * blockDim.x + threadIdx.x;
    int node = gid >> 5;
    if (node >= M) return;
    int lane = gid & 31;

    int beg = __ldg(&g_rowstart[node]);
    int end = __ldg(&g_rowstart[node + 1]);

    float4 a0 = make_float4(0.f, 0.f, 0.f, 0.f);
    float4 a1 = make_float4(0.f, 0.f, 0.f, 0.f);

    int i = beg;
    for (; i + 3 < end; i += 4) {
        int2 e0 = __ldg(&g_edges[i]);
        int2 e1 = __ldg(&g_edges[i + 1]);
        int2 e2 = __ldg(&g_edges[i + 2]);
        int2 e3 = __ldg(&g_edges[i + 3]);
        half4 v0 = *(const half4*)(Hin + (size_t)e0.x * NHID + lane * 4);
        half4 v1 = *(const half4*)(Hin + (size_t)e1.x * NHID + lane * 4);
        half4 v2 = *(const half4*)(Hin + (size_t)e2.x * NHID + lane * 4);
        half4 v3 = *(const half4*)(Hin + (size_t)e3.x * NHID + lane * 4);
        float w0 = __int_as_float(e0.y), w1 = __int_as_float(e1.y);
        float w2 = __int_as_float(e2.y), w3 = __int_as_float(e3.y);
        float2 f0a = __half22float2(v0.a), f0b = __half22float2(v0.b);
        float2 f1a = __half22float2(v1.a), f1b = __half22float2(v1.b);
        a0.x = fmaf(w0, f0a.x, a0.x); a0.y = fmaf(w0, f0a.y, a0.y);
        a0.z = fmaf(w0, f0b.x, a0.z); a0.w = fmaf(w0, f0b.y, a0.w);
        a1.x = fmaf(w1, f1a.x, a1.x); a1.y = fmaf(w1, f1a.y, a1.y);
        a1.z = fmaf(w1, f1b.x, a1.z); a1.w = fmaf(w1, f1b.y, a1.w);
        float2 f2a = __half22float2(v2.a), f2b = __half22float2(v2.b);
        float2 f3a = __half22float2(v3.a), f3b = __half22float2(v3.b);
        a0.x = fmaf(w2, f2a.x, a0.x); a0.y = fmaf(w2, f2a.y, a0.y);
        a0.z = fmaf(w2, f2b.x, a0.z); a0.w = fmaf(w2, f2b.y, a0.w);
        a1.x = fmaf(w3, f3a.x, a1.x); a1.y = fmaf(w3, f3a.y, a1.y);
        a1.z = fmaf(w3, f3b.x, a1.z); a1.w = fmaf(w3, f3b.y, a1.w);
    }
    for (; i < end; i++) {
        int2 e0 = __ldg(&g_edges[i]);
        half4 v0 = *(const half4*)(Hin + (size_t)e0.x * NHID + lane * 4);
        float w0 = __int_as_float(e0.y);
        float2 f0a = __half22float2(v0.a), f0b = __half22float2(v0.b);
        a0.x = fmaf(w0, f0a.x, a0.x); a0.y = fmaf(w0, f0a.y, a0.y);
        a0.z = fmaf(w0, f0b.x, a0.z); a0.w = fmaf(w0, f0b.y, a0.w);
    }

    float4 v;
    float4 b = *(const float4*)(b0 + lane * 4);
    v.x = a0.x + a1.x + b.x;
    v.y = a0.y + a1.y + b.y;
    v.z = a0.z + a1.z + b.z;
    v.w = a0.w + a1.w + b.w;

    float ss = v.x * v.x + v.y * v.y + v.z * v.z + v.w * v.w;
#pragma unroll
    for (int off = 16; off > 0; off >>= 1)
        ss += __shfl_xor_sync(0xffffffffu, ss, off);

    float scale = 1.0f / fmaxf(sqrtf(ss), 1e-12f);

    half4 o;
    o.a = __floats2half2_rn(fmaxf(v.x * scale, 0.f), fmaxf(v.y * scale, 0.f));
    o.b = __floats2half2_rn(fmaxf(v.z * scale, 0.f), fmaxf(v.w * scale, 0.f));
    *(half4*)(Hout + (size_t)node * NHID + lane * 4) = o;
}

// ---------------------------------------------------------------------------
// GEMM2 via WMMA split-fp16: Z[M, Z2LD(pad)] = H[M,128] @ W1[128,40].
// Output rows padded to 128B so spmm2 gathers hit exactly one L2 line.
// ---------------------------------------------------------------------------
#define G2_LDH 136
#define G2_LDW 56
#define G2_WHI (128 * G2_LDH)
#define G2_WLO (G2_WHI + 128 * G2_LDW)
#define G2_SMEM ((G2_WLO + 128 * G2_LDW) * 2)   // 63488 bytes

__global__ __launch_bounds__(256, 2)
void gemm2_wmma_kernel(const __half* __restrict__ H, const float* __restrict__ W,
                       __half* __restrict__ Z, int M)
{
    extern __shared__ __align__(16) char sm2[];
    __half* sh = (__half*)sm2;

    int tid  = threadIdx.x;
    int warp = tid >> 5;
    int lane = tid & 31;
    int node0 = blockIdx.x * 128;

    for (int q = tid; q < 128 * 16; q += 256) {
        int row = q >> 4, c8 = (q & 15) * 8;
        int gn = node0 + row;
        uint4 v = make_uint4(0u, 0u, 0u, 0u);
        if (gn < M) v = *(const uint4*)(H + (size_t)gn * NHID + c8);
        *(uint4*)(sh + row * G2_LDH + c8) = v;
    }

    for (int q = tid; q < 128 * G2_LDW; q += 256) {
        int k = q / G2_LDW, c = q - k * G2_LDW;
        __half hi = __float2half_rn(0.f), lo = hi;
        if (c < NCLASS) {
            float f = W[(size_t)k * NCLASS + c];
            hi = __float2half_rn(f);
            lo = __float2half_rn(f - __half2float(hi));
        }
        sh[G2_WHI + k * G2_LDW + c] = hi;
        sh[G2_WLO + k * G2_LDW + c] = lo;
    }
    __syncthreads();

    wmma::fragment<wmma::accumulator, 16, 16, 16, float> acc[3];
#pragma unroll
    for (int j = 0; j < 3; j++) wmma::fill_fragment(acc[j], 0.0f);

    const __half* hrow = sh + (warp * 16) * G2_LDH;
#pragma unroll
    for (int kk = 0; kk < 128; kk += 16) {
        wmma::fragment<wmma::matrix_a, 16, 16, 16, __half, wmma::row_major> a;
        wmma::load_matrix_sync(a, hrow + kk, G2_LDH);
#pragma unroll
        for (int j = 0; j < 3; j++) {
            wmma::fragment<wmma::matrix_b, 16, 16, 16, __half, wmma::row_major> bh, bl;
            wmma::load_matrix_sync(bh, sh + G2_WHI + kk * G2_LDW + j * 16, G2_LDW);
            wmma::load_matrix_sync(bl, sh + G2_WLO + kk * G2_LDW + j * 16, G2_LDW);
            wmma::mma_sync(acc[j], a, bh, acc[j]);
            wmma::mma_sync(acc[j], a, bl, acc[j]);
        }
    }
    __syncthreads();

    float* st = (float*)sm2 + warp * (16 * G2_LDW);
#pragma unroll
    for (int j = 0; j < 3; j++)
        wmma::store_matrix_sync(st + j * 16, acc[j], G2_LDW, wmma::mem_row_major);
    __syncwarp();

    int row = lane >> 1;
    int cbase = (lane & 1) * 20;
    int gn = node0 + warp * 16 + row;
    if (gn < M) {
        const float* srow = st + row * G2_LDW + cbase;
        __half* dst = Z + (size_t)gn * Z2LD + cbase;
#pragma unroll
        for (int c = 0; c < 20; c += 2) {
            __half2 h = __floats2half2_rn(srow[c], srow[c + 1]);
            *(uint32_t*)(dst + c) = *(uint32_t*)&h;
        }
    }
}

// ---------------------------------------------------------------------------
// Fused SPMM2 + bias + log_softmax. Warp per dst node. Lane l<20 owns classes
// {2l, 2l+1}; one half2 load per edge (padded 128B rows -> single L2 line,
// pad lanes load in-bounds garbage that is never consumed). MLP=4.
// ---------------------------------------------------------------------------
__global__ __launch_bounds__(256) void spmm2lsm_kernel(
    const __half* __restrict__ Zin, const float* __restrict__ b1,
    float* __restrict__ out, int M)
{
    int gid = blockIdx.x * blockDim.x + threadIdx.x;
    int node = gid >> 5;
    if (node >= M) return;
    int lane = gid & 31;
    bool act = lane < 20;

    int beg = __ldg(&g_rowstart[node]);
    int end = __ldg(&g_rowstart[node + 1]);

    float2 a0 = make_float2(0.f, 0.f);
    float2 a1 = make_float2(0.f, 0.f);

    int i = beg;
    for (; i + 3 < end; i += 4) {
        int2 e0 = __ldg(&g_edges[i]);
        int2 e1 = __ldg(&g_edges[i + 1]);
        int2 e2 = __ldg(&g_edges[i + 2]);
        int2 e3 = __ldg(&g_edges[i + 3]);
        __half2 v0 = *(const __half2*)(Zin + (size_t)e0.x * Z2LD + lane * 2);
        __half2 v1 = *(const __half2*)(Zin + (size_t)e1.x * Z2LD + lane * 2);
        __half2 v2 = *(const __half2*)(Zin + (size_t)e2.x * Z2LD + lane * 2);
        __half2 v3 = *(const __half2*)(Zin + (size_t)e3.x * Z2LD + lane * 2);
        float w0 = __int_as_float(e0.y), w1 = __int_as_float(e1.y);
        float w2 = __int_as_float(e2.y), w3 = __int_as_float(e3.y);
        float2 f0 = __half22float2(v0), f1 = __half22float2(v1);
        float2 f2 = __half22float2(v2), f3 = __half22float2(v3);
        a0.x = fmaf(w0, f0.x, a0.x); a0.y = fmaf(w0, f0.y, a0.y);
        a1.x = fmaf(w1, f1.x, a1.x); a1.y = fmaf(w1, f1.y, a1.y);
        a0.x = fmaf(w2, f2.x, a0.x); a0.y = fmaf(w2, f2.y, a0.y);
        a1.x = fmaf(w3, f3.x, a1.x); a1.y = fmaf(w3, f3.y, a1.y);
    }
    for (; i < end; i++) {
        int2 e0 = __ldg(&g_edges[i]);
        __half2 v0 = *(const __half2*)(Zin + (size_t)e0.x * Z2LD + lane * 2);
        float w0 = __int_as_float(e0.y);
        float2 f0 = __half22float2(v0);
        a0.x = fmaf(w0, f0.x, a0.x); a0.y = fmaf(w0, f0.y, a0.y);
    }

    float2 z = make_float2(-INFINITY, -INFINITY);
    if (act) {
        float2 bb = *(const float2*)(b1 + lane * 2);
        z.x = a0.x + a1.x + bb.x;
        z.y = a0.y + a1.y + bb.y;
    }

    float m = fmaxf(z.x, z.y);
#pragma unroll
    for (int off = 16; off > 0; off >>= 1)
        m = fmaxf(m, __shfl_xor_sync(0xffffffffu, m, off));

    float es = act ? (expf(z.x - m) + expf(z.y - m)) : 0.f;
#pragma unroll
    for (int off = 16; off > 0; off >>= 1)
        es += __shfl_xor_sync(0xffffffffu, es, off);

    float lse = logf(es);
    if (act) {
        float2 o = make_float2(z.x - m - lse, z.y - m - lse);
        *(float2*)(out + (size_t)node * NCLASS + lane * 2) = o;
    }
}

// ---------------------------------------------------------------------------
extern "C" void kernel_launch(void* const* d_in, const int* in_sizes, int n_in,
                              void* d_out, int out_size)
{
    const float* x    = (const float*)d_in[0];
    const int*   esrc = (const int*)  d_in[1];
    const int*   edst = (const int*)  d_in[2];
    const float* ew   = (const float*)d_in[3];
    const float* W0   = (const float*)d_in[4];
    const float* b0   = (const float*)d_in[5];
    const float* W1   = (const float*)d_in[6];
    const float* b1   = (const float*)d_in[7];
    float* out = (float*)d_out;

    int M = in_sizes[0] / NFEAT;   // 100000
    int E = in_sizes[1];           // 3200000

    __half *H0p, *H1, *Z2p;
    cudaGetSymbolAddress((void**)&H0p, g_H0p);
    cudaGetSymbolAddress((void**)&H1,  g_H1);
    cudaGetSymbolAddress((void**)&Z2p, g_Z2p);

    cudaFuncSetAttribute(gemm1_wmma_kernel,
                         cudaFuncAttributeMaxDynamicSharedMemorySize, G1_SMEM);
    cudaFuncSetAttribute(gemm2_wmma_kernel,
                         cudaFuncAttributeMaxDynamicSharedMemorySize, G2_SMEM);

    // CSR build (cnt arrives zeroed: zero-init at load + scan re-zeroes it)
    hist_kernel<<<(E + 255) / 256, 256>>>(edst, E);
    scan_kernel<<<1, 1024>>>(M);
    scatter_kernel<<<(E + 255) / 256, 256>>>(esrc, edst, ew, E);

    // Layer 1 dense projection via double-buffered WMMA split-bf16 (fp16 out)
    gemm1_wmma_kernel<<<(M + 127) / 128, 256, G1_SMEM>>>(x, W0, H0p, M);

    // SPMM1 + bias + l2norm + relu (warp/node, MLP=4, fp16 out)
    {
        long long threads = (long long)M * 32;
        spmm1norm_kernel<<<(int)((threads + 255) / 256), 256>>>(H0p, b0, H1, M);
    }

    // Layer 2 dense projection via WMMA split-fp16 (fp16 in, padded fp16 out)
    gemm2_wmma_kernel<<<(M + 127) / 128, 256, G2_SMEM>>>(H1, W1, Z2p, M);

    // SPMM2 + bias + log_softmax (warp/node, half2 gather, MLP=4)
    {
        long long threads = (long long)M * 32;
        spmm2lsm_kernel<<<(int)((threads + 255) / 256), 256>>>(Z2p, b1, out, M);
    }
}

// round 17
// speedup vs baseline: 1.0880x; 1.0880x over previous
#include <cuda_runtime.h>
#include <cuda_fp16.h>
#include <cuda_bf16.h>
#include <mma.h>
#include <math.h>
#include <stdint.h>

using namespace nvcuda;

#define NFEAT  256
#define NHID   128
#define NCLASS 40
#define Z2LD   64          // padded Z2p row stride (halves) = 128 bytes
#define MAXN   100000
#define MAXE   3200000

struct alignas(8) half4 { __half2 a, b; };

// Scratch (allocation-free: __device__ globals).
__device__ __align__(256) __half g_H0p[MAXN * NHID];   // x @ W0 (fp16)
__device__ __align__(256) __half g_H1 [MAXN * NHID];   // normalized relu hidden (fp16)
__device__ __align__(256) __half g_Z2p[MAXN * Z2LD];   // H1 @ W1 (fp16, 128B rows)
__device__ __align__(256) int    g_cnt[MAXN];          // per-dst degree histogram
__device__ __align__(256) int    g_rowstart[MAXN + 1]; // CSR row pointers
__device__ __align__(256) int    g_cursor[MAXN];       // scatter cursors
__device__ __align__(256) int2   g_edges[MAXE];        // CSR payload: {src, w bits}

// Split a float4 into packed bf16 hi (uint2) and lo (uint2).
__device__ __forceinline__ void split4(float4 v, uint2& hi, uint2& lo) {
    __nv_bfloat162 h01 = __floats2bfloat162_rn(v.x, v.y);
    __nv_bfloat162 h23 = __floats2bfloat162_rn(v.z, v.w);
    hi.x = *(uint32_t*)&h01;
    hi.y = *(uint32_t*)&h23;
    float l0 = v.x - __bfloat162float(__low2bfloat16(h01));
    float l1 = v.y - __bfloat162float(__high2bfloat16(h01));
    float l2 = v.z - __bfloat162float(__low2bfloat16(h23));
    float l3 = v.w - __bfloat162float(__high2bfloat16(h23));
    __nv_bfloat162 q01 = __floats2bfloat162_rn(l0, l1);
    __nv_bfloat162 q23 = __floats2bfloat162_rn(l2, l3);
    lo.x = *(uint32_t*)&q01;
    lo.y = *(uint32_t*)&q23;
}

// ---------------------------------------------------------------------------
// GEMM1 via WMMA split-bf16, DOUBLE-BUFFERED (unchanged).
// ---------------------------------------------------------------------------
#define G1_LDA 40
#define G1_LDB 136
#define G1_ALO   (128 * G1_LDA)
#define G1_ABUF  (2 * 128 * G1_LDA)
#define G1_BLO   (32 * G1_LDB)
#define G1_BBUF  (2 * 32 * G1_LDB)
#define G1_BBASE (2 * G1_ABUF)
#define G1_SMEM  ((2 * G1_ABUF + 2 * G1_BBUF) * 2)   // 75776 bytes

__global__ __launch_bounds__(256, 2)
void gemm1_wmma_kernel(const float* __restrict__ A, const float* __restrict__ B,
                       __half* __restrict__ C, int M)
{
    extern __shared__ __align__(16) char sm[];
    __nv_bfloat16* sb = (__nv_bfloat16*)sm;

    int tid  = threadIdx.x;
    int warp = tid >> 5;
    int lane = tid & 31;
    int wm = warp & 3;
    int wn = warp >> 2;
    int blockRow = blockIdx.x * 128;

    int aRow[4], aC4[4], bRow[4], bC4[4];
    bool aOk[4];
#pragma unroll
    for (int i = 0; i < 4; i++) {
        int idx = tid + i * 256;
        aRow[i] = idx >> 3;  aC4[i] = (idx & 7) * 4;
        aOk[i]  = (blockRow + aRow[i]) < M;
        bRow[i] = idx >> 5;  bC4[i] = (idx & 31) * 4;
    }

    wmma::fragment<wmma::accumulator, 16, 16, 16, float> acc[2][4];
#pragma unroll
    for (int i = 0; i < 2; i++)
#pragma unroll
        for (int j = 0; j < 4; j++) wmma::fill_fragment(acc[i][j], 0.0f);

    float4 pa[4], pb[4];

#pragma unroll
    for (int i = 0; i < 4; i++) {
        pa[i] = aOk[i] ? *(const float4*)(A + (size_t)(blockRow + aRow[i]) * NFEAT + aC4[i])
                       : make_float4(0.f, 0.f, 0.f, 0.f);
        pb[i] = *(const float4*)(B + (size_t)bRow[i] * NHID + bC4[i]);
    }
#pragma unroll
    for (int i = 0; i < 4; i++) {
        uint2 hi, lo;
        split4(pa[i], hi, lo);
        *(uint2*)(sb + aRow[i] * G1_LDA + aC4[i]) = hi;
        *(uint2*)(sb + G1_ALO + aRow[i] * G1_LDA + aC4[i]) = lo;
    }
#pragma unroll
    for (int i = 0; i < 4; i++) {
        uint2 hi, lo;
        split4(pb[i], hi, lo);
        *(uint2*)(sb + G1_BBASE + bRow[i] * G1_LDB + bC4[i]) = hi;
        *(uint2*)(sb + G1_BBASE + G1_BLO + bRow[i] * G1_LDB + bC4[i]) = lo;
    }
#pragma unroll
    for (int i = 0; i < 4; i++) {
        pa[i] = aOk[i] ? *(const float4*)(A + (size_t)(blockRow + aRow[i]) * NFEAT + 32 + aC4[i])
                       : make_float4(0.f, 0.f, 0.f, 0.f);
        pb[i] = *(const float4*)(B + (size_t)(32 + bRow[i]) * NHID + bC4[i]);
    }
    __syncthreads();

    for (int c = 0; c < 8; c++) {
        int cur = c & 1;
        __nv_bfloat16* abuf = sb + cur * G1_ABUF;
        __nv_bfloat16* bbuf = sb + G1_BBASE + cur * G1_BBUF;

        if (c < 7) {
            __nv_bfloat16* an = sb + (cur ^ 1) * G1_ABUF;
            __nv_bfloat16* bn = sb + G1_BBASE + (cur ^ 1) * G1_BBUF;
#pragma unroll
            for (int i = 0; i < 4; i++) {
                uint2 hi, lo;
                split4(pa[i], hi, lo);
                *(uint2*)(an + aRow[i] * G1_LDA + aC4[i]) = hi;
                *(uint2*)(an + G1_ALO + aRow[i] * G1_LDA + aC4[i]) = lo;
            }
#pragma unroll
            for (int i = 0; i < 4; i++) {
                uint2 hi, lo;
                split4(pb[i], hi, lo);
                *(uint2*)(bn + bRow[i] * G1_LDB + bC4[i]) = hi;
                *(uint2*)(bn + G1_BLO + bRow[i] * G1_LDB + bC4[i]) = lo;
            }
            if (c < 6) {
                int k0 = (c + 2) * 32;
#pragma unroll
                for (int i = 0; i < 4; i++) {
                    pa[i] = aOk[i] ? *(const float4*)(A + (size_t)(blockRow + aRow[i]) * NFEAT + k0 + aC4[i])
                                   : make_float4(0.f, 0.f, 0.f, 0.f);
                    pb[i] = *(const float4*)(B + (size_t)(k0 + bRow[i]) * NHID + bC4[i]);
                }
            }
        }

#pragma unroll
        for (int kk = 0; kk < 32; kk += 16) {
            wmma::fragment<wmma::matrix_a, 16, 16, 16, __nv_bfloat16, wmma::row_major> a_hi[2], a_lo[2];
#pragma unroll
            for (int i = 0; i < 2; i++) {
                const __nv_bfloat16* pa_ = abuf + (wm * 32 + i * 16) * G1_LDA + kk;
                wmma::load_matrix_sync(a_hi[i], pa_, G1_LDA);
                wmma::load_matrix_sync(a_lo[i], pa_ + G1_ALO, G1_LDA);
            }
#pragma unroll
            for (int j = 0; j < 4; j++) {
                wmma::fragment<wmma::matrix_b, 16, 16, 16, __nv_bfloat16, wmma::row_major> b_hi, b_lo;
                const __nv_bfloat16* pb_ = bbuf + kk * G1_LDB + wn * 64 + j * 16;
                wmma::load_matrix_sync(b_hi, pb_, G1_LDB);
                wmma::load_matrix_sync(b_lo, pb_ + G1_BLO, G1_LDB);
#pragma unroll
                for (int i = 0; i < 2; i++) {
                    wmma::mma_sync(acc[i][j], a_hi[i], b_hi, acc[i][j]);
                    wmma::mma_sync(acc[i][j], a_hi[i], b_lo, acc[i][j]);
                    wmma::mma_sync(acc[i][j], a_lo[i], b_hi, acc[i][j]);
                }
            }
        }
        __syncthreads();
    }

    float* st = (float*)sm + wm * (32 * 64);
#pragma unroll
    for (int ph = 0; ph < 2; ph++) {
        if (wn == ph) {
#pragma unroll
            for (int i = 0; i < 2; i++)
#pragma unroll
                for (int j = 0; j < 4; j++)
                    wmma::store_matrix_sync(st + (i * 16) * 64 + j * 16, acc[i][j], 64,
                                            wmma::mem_row_major);
            __syncwarp();
            int row = blockRow + wm * 32 + lane;
            if (row < M) {
                __half* dst = C + (size_t)row * NHID + wn * 64;
                const float* srow = st + lane * 64;
#pragma unroll
                for (int cc = 0; cc < 64; cc += 8) {
                    float4 f0 = *(const float4*)(srow + cc);
                    float4 f1 = *(const float4*)(srow + cc + 4);
                    uint4 o;
                    __half2 h;
                    h = __floats2half2_rn(f0.x, f0.y); o.x = *(uint32_t*)&h;
                    h = __floats2half2_rn(f0.z, f0.w); o.y = *(uint32_t*)&h;
                    h = __floats2half2_rn(f1.x, f1.y); o.z = *(uint32_t*)&h;
                    h = __floats2half2_rn(f1.z, f1.w); o.w = *(uint32_t*)&h;
                    *(uint4*)(dst + cc) = o;
                }
            }
        }
        __syncthreads();
    }
}

// ---------------------------------------------------------------------------
// CSR build step 1: histogram of destination nodes.
// ---------------------------------------------------------------------------
__global__ __launch_bounds__(256) void hist_kernel(
    const int* __restrict__ dst, int E)
{
    int e = blockIdx.x * blockDim.x + threadIdx.x;
    if (e < E) atomicAdd(&g_cnt[__ldg(dst + e)], 1);
}

// ---------------------------------------------------------------------------
// CSR build step 2: exclusive prefix sum over N counts. Single block, 1024 thr.
// ---------------------------------------------------------------------------
__global__ __launch_bounds__(1024) void scan_kernel(int N)
{
    __shared__ int s[1024];
    int t = threadIdx.x;
    int chunk = (N + 1023) / 1024;
    int beg = t * chunk;
    int end = min(beg + chunk, N);

    int sum = 0;
    for (int i = beg; i < end; i++) sum += g_cnt[i];
    s[t] = sum;
    __syncthreads();

#pragma unroll
    for (int off = 1; off < 1024; off <<= 1) {
        int v = (t >= off) ? s[t - off] : 0;
        __syncthreads();
        s[t] += v;
        __syncthreads();
    }

    int base = s[t] - sum;   // exclusive prefix
    for (int i = beg; i < end; i++) {
        g_rowstart[i] = base;
        g_cursor[i]   = base;
        base += g_cnt[i];
    }
    if (t == 1023) g_rowstart[N] = s[1023];
}

// ---------------------------------------------------------------------------
// CSR build step 3: scatter (src, w) into per-dst segments.
// ---------------------------------------------------------------------------
__global__ __launch_bounds__(256) void scatter_kernel(
    const int* __restrict__ src, const int* __restrict__ dst,
    const float* __restrict__ w, int E)
{
    int e = blockIdx.x * blockDim.x + threadIdx.x;
    if (e >= E) return;
    int d = __ldg(dst + e);
    int pos = atomicAdd(&g_cursor[d], 1);
    g_edges[pos] = make_int2(__ldg(src + e), __float_as_int(__ldg(w + e)));
}

// ---------------------------------------------------------------------------
// Fused SPMM1 + bias + L2 normalize + ReLU (round-13 form, unchanged).
// ---------------------------------------------------------------------------
__global__ __launch_bounds__(256) void spmm1norm_kernel(
    const __half* __restrict__ Hin, const float* __restrict__ b0,
    __half* __restrict__ Hout, int M)
{
    int gid = blockIdx.x * blockDim.x + threadIdx.x;
    int node = gid >> 5;
    if (node >= M) return;
    int lane = gid & 31;

    int beg = __ldg(&g_rowstart[node]);
    int end = __ldg(&g_rowstart[node + 1]);

    float4 a0 = make_float4(0.f, 0.f, 0.f, 0.f);
    float4 a1 = make_float4(0.f, 0.f, 0.f, 0.f);

    int i = beg;
    for (; i + 3 < end; i += 4) {
        int2 e0 = __ldg(&g_edges[i]);
        int2 e1 = __ldg(&g_edges[i + 1]);
        int2 e2 = __ldg(&g_edges[i + 2]);
        int2 e3 = __ldg(&g_edges[i + 3]);
        half4 v0 = *(const half4*)(Hin + (size_t)e0.x * NHID + lane * 4);
        half4 v1 = *(const half4*)(Hin + (size_t)e1.x * NHID + lane * 4);
        half4 v2 = *(const half4*)(Hin + (size_t)e2.x * NHID + lane * 4);
        half4 v3 = *(const half4*)(Hin + (size_t)e3.x * NHID + lane * 4);
        float w0 = __int_as_float(e0.y), w1 = __int_as_float(e1.y);
        float w2 = __int_as_float(e2.y), w3 = __int_as_float(e3.y);
        float2 f0a = __half22float2(v0.a), f0b = __half22float2(v0.b);
        float2 f1a = __half22float2(v1.a), f1b = __half22float2(v1.b);
        a0.x = fmaf(w0, f0a.x, a0.x); a0.y = fmaf(w0, f0a.y, a0.y);
        a0.z = fmaf(w0, f0b.x, a0.z); a0.w = fmaf(w0, f0b.y, a0.w);
        a1.x = fmaf(w1, f1a.x, a1.x); a1.y = fmaf(w1, f1a.y, a1.y);
        a1.z = fmaf(w1, f1b.x, a1.z); a1.w = fmaf(w1, f1b.y, a1.w);
        float2 f2a = __half22float2(v2.a), f2b = __half22float2(v2.b);
        float2 f3a = __half22float2(v3.a), f3b = __half22float2(v3.b);
        a0.x = fmaf(w2, f2a.x, a0.x); a0.y = fmaf(w2, f2a.y, a0.y);
        a0.z = fmaf(w2, f2b.x, a0.z); a0.w = fmaf(w2, f2b.y, a0.w);
        a1.x = fmaf(w3, f3a.x, a1.x); a1.y = fmaf(w3, f3a.y, a1.y);
        a1.z = fmaf(w3, f3b.x, a1.z); a1.w = fmaf(w3, f3b.y, a1.w);
    }
    for (; i < end; i++) {
        int2 e0 = __ldg(&g_edges[i]);
        half4 v0 = *(const half4*)(Hin + (size_t)e0.x * NHID + lane * 4);
        float w0 = __int_as_float(e0.y);
        float2 f0a = __half22float2(v0.a), f0b = __half22float2(v0.b);
        a0.x = fmaf(w0, f0a.x, a0.x); a0.y = fmaf(w0, f0a.y, a0.y);
        a0.z = fmaf(w0, f0b.x, a0.z); a0.w = fmaf(w0, f0b.y, a0.w);
    }

    float4 v;
    float4 b = *(const float4*)(b0 + lane * 4);
    v.x = a0.x + a1.x + b.x;
    v.y = a0.y + a1.y + b.y;
    v.z = a0.z + a1.z + b.z;
    v.w = a0.w + a1.w + b.w;

    float ss = v.x * v.x + v.y * v.y + v.z * v.z + v.w * v.w;
#pragma unroll
    for (int off = 16; off > 0; off >>= 1)
        ss += __shfl_xor_sync(0xffffffffu, ss, off);

    float scale = 1.0f / fmaxf(sqrtf(ss), 1e-12f);

    half4 o;
    o.a = __floats2half2_rn(fmaxf(v.x * scale, 0.f), fmaxf(v.y * scale, 0.f));
    o.b = __floats2half2_rn(fmaxf(v.z * scale, 0.f), fmaxf(v.w * scale, 0.f));
    *(half4*)(Hout + (size_t)node * NHID + lane * 4) = o;
}

// ---------------------------------------------------------------------------
// GEMM2 via WMMA split-fp16: Z[M, Z2LD(pad)] = H[M,128] @ W1[128,40].
// Output rows padded to 128B lines for the spmm2 gather.
// ---------------------------------------------------------------------------
#define G2_LDH 136
#define G2_LDW 56
#define G2_WHI (128 * G2_LDH)
#define G2_WLO (G2_WHI + 128 * G2_LDW)
#define G2_SMEM ((G2_WLO + 128 * G2_LDW) * 2)   // 63488 bytes

__global__ __launch_bounds__(256, 2)
void gemm2_wmma_kernel(const __half* __restrict__ H, const float* __restrict__ W,
                       __half* __restrict__ Z, int M)
{
    extern __shared__ __align__(16) char sm2[];
    __half* sh = (__half*)sm2;

    int tid  = threadIdx.x;
    int warp = tid >> 5;
    int lane = tid & 31;
    int node0 = blockIdx.x * 128;

    for (int q = tid; q < 128 * 16; q += 256) {
        int row = q >> 4, c8 = (q & 15) * 8;
        int gn = node0 + row;
        uint4 v = make_uint4(0u, 0u, 0u, 0u);
        if (gn < M) v = *(const uint4*)(H + (size_t)gn * NHID + c8);
        *(uint4*)(sh + row * G2_LDH + c8) = v;
    }

    for (int q = tid; q < 128 * G2_LDW; q += 256) {
        int k = q / G2_LDW, c = q - k * G2_LDW;
        __half hi = __float2half_rn(0.f), lo = hi;
        if (c < NCLASS) {
            float f = W[(size_t)k * NCLASS + c];
            hi = __float2half_rn(f);
            lo = __float2half_rn(f - __half2float(hi));
        }
        sh[G2_WHI + k * G2_LDW + c] = hi;
        sh[G2_WLO + k * G2_LDW + c] = lo;
    }
    __syncthreads();

    wmma::fragment<wmma::accumulator, 16, 16, 16, float> acc[3];
#pragma unroll
    for (int j = 0; j < 3; j++) wmma::fill_fragment(acc[j], 0.0f);

    const __half* hrow = sh + (warp * 16) * G2_LDH;
#pragma unroll
    for (int kk = 0; kk < 128; kk += 16) {
        wmma::fragment<wmma::matrix_a, 16, 16, 16, __half, wmma::row_major> a;
        wmma::load_matrix_sync(a, hrow + kk, G2_LDH);
#pragma unroll
        for (int j = 0; j < 3; j++) {
            wmma::fragment<wmma::matrix_b, 16, 16, 16, __half, wmma::row_major> bh, bl;
            wmma::load_matrix_sync(bh, sh + G2_WHI + kk * G2_LDW + j * 16, G2_LDW);
            wmma::load_matrix_sync(bl, sh + G2_WLO + kk * G2_LDW + j * 16, G2_LDW);
            wmma::mma_sync(acc[j], a, bh, acc[j]);
            wmma::mma_sync(acc[j], a, bl, acc[j]);
        }
    }
    __syncthreads();

    float* st = (float*)sm2 + warp * (16 * G2_LDW);
#pragma unroll
    for (int j = 0; j < 3; j++)
        wmma::store_matrix_sync(st + j * 16, acc[j], G2_LDW, wmma::mem_row_major);
    __syncwarp();

    int row = lane >> 1;
    int cbase = (lane & 1) * 20;
    int gn = node0 + warp * 16 + row;
    if (gn < M) {
        const float* srow = st + row * G2_LDW + cbase;
        __half* dst = Z + (size_t)gn * Z2LD + cbase;
#pragma unroll
        for (int c = 0; c < 20; c += 2) {
            __half2 h = __floats2half2_rn(srow[c], srow[c + 1]);
            *(uint32_t*)(dst + c) = *(uint32_t*)&h;
        }
    }
}

// ---------------------------------------------------------------------------
// Fused SPMM2 + bias + log_softmax. Warp per dst node. Lane l<20 owns classes
// {2l, 2l+1}; ONE half2 load per edge (padded 128B rows -> one L2 line;
// pad lanes read in-bounds garbage never consumed). Unroll kept at 2 — the
// 4-deep variant regressed twice (rounds 14, 16).
// ---------------------------------------------------------------------------
__global__ __launch_bounds__(256) void spmm2lsm_kernel(
    const __half* __restrict__ Zin, const float* __restrict__ b1,
    float* __restrict__ out, int M)
{
    int gid = blockIdx.x * blockDim.x + threadIdx.x;
    int node = gid >> 5;
    if (node >= M) return;
    int lane = gid & 31;
    bool act = lane < 20;

    int beg = __ldg(&g_rowstart[node]);
    int end = __ldg(&g_rowstart[node + 1]);

    float2 a0 = make_float2(0.f, 0.f);
    float2 a1 = make_float2(0.f, 0.f);

    int i = beg;
    for (; i + 1 < end; i += 2) {
        int2 e0 = __ldg(&g_edges[i]);
        int2 e1 = __ldg(&g_edges[i + 1]);
        __half2 v0 = *(const __half2*)(Zin + (size_t)e0.x * Z2LD + lane * 2);
        __half2 v1 = *(const __half2*)(Zin + (size_t)e1.x * Z2LD + lane * 2);
        float w0 = __int_as_float(e0.y);
        float w1 = __int_as_float(e1.y);
        float2 f0 = __half22float2(v0);
        float2 f1 = __half22float2(v1);
        a0.x = fmaf(w0, f0.x, a0.x); a0.y = fmaf(w0, f0.y, a0.y);
        a1.x = fmaf(w1, f1.x, a1.x); a1.y = fmaf(w1, f1.y, a1.y);
    }
    if (i < end) {
        int2 e0 = __ldg(&g_edges[i]);
        __half2 v0 = *(const __half2*)(Zin + (size_t)e0.x * Z2LD + lane * 2);
        float w0 = __int_as_float(e0.y);
        float2 f0 = __half22float2(v0);
        a0.x = fmaf(w0, f0.x, a0.x); a0.y = fmaf(w0, f0.y, a0.y);
    }

    float2 z = make_float2(-INFINITY, -INFINITY);
    if (act) {
        float2 bb = *(const float2*)(b1 + lane * 2);
        z.x = a0.x + a1.x + bb.x;
        z.y = a0.y + a1.y + bb.y;
    }

    float m = fmaxf(z.x, z.y);
#pragma unroll
    for (int off = 16; off > 0; off >>= 1)
        m = fmaxf(m, __shfl_xor_sync(0xffffffffu, m, off));

    float es = act ? (expf(z.x - m) + expf(z.y - m)) : 0.f;
#pragma unroll
    for (int off = 16; off > 0; off >>= 1)
        es += __shfl_xor_sync(0xffffffffu, es, off);

    float lse = logf(es);
    if (act) {
        float2 o = make_float2(z.x - m - lse, z.y - m - lse);
        *(float2*)(out + (size_t)node * NCLASS + lane * 2) = o;
    }
}

// ---------------------------------------------------------------------------
extern "C" void kernel_launch(void* const* d_in, const int* in_sizes, int n_in,
                              void* d_out, int out_size)
{
    const float* x    = (const float*)d_in[0];
    const int*   esrc = (const int*)  d_in[1];
    const int*   edst = (const int*)  d_in[2];
    const float* ew   = (const float*)d_in[3];
    const float* W0   = (const float*)d_in[4];
    const float* b0   = (const float*)d_in[5];
    const float* W1   = (const float*)d_in[6];
    const float* b1   = (const float*)d_in[7];
    float* out = (float*)d_out;

    int M = in_sizes[0] / NFEAT;   // 100000
    int E = in_sizes[1];           // 3200000

    __half *H0p, *H1, *Z2p;
    int* cnt;
    cudaGetSymbolAddress((void**)&H0p, g_H0p);
    cudaGetSymbolAddress((void**)&H1,  g_H1);
    cudaGetSymbolAddress((void**)&Z2p, g_Z2p);
    cudaGetSymbolAddress((void**)&cnt, g_cnt);

    cudaFuncSetAttribute(gemm1_wmma_kernel,
                         cudaFuncAttributeMaxDynamicSharedMemorySize, G1_SMEM);
    cudaFuncSetAttribute(gemm2_wmma_kernel,
                         cudaFuncAttributeMaxDynamicSharedMemorySize, G2_SMEM);

    // CSR build (round-15 order, explicit memset)
    cudaMemsetAsync(cnt, 0, (size_t)M * sizeof(int), 0);
    hist_kernel<<<(E + 255) / 256, 256>>>(edst, E);
    scan_kernel<<<1, 1024>>>(M);
    scatter_kernel<<<(E + 255) / 256, 256>>>(esrc, edst, ew, E);

    // Layer 1 dense projection via double-buffered WMMA split-bf16 (fp16 out)
    gemm1_wmma_kernel<<<(M + 127) / 128, 256, G1_SMEM>>>(x, W0, H0p, M);

    // SPMM1 + bias + l2norm + relu (warp/node, MLP=4, fp16 out)
    {
        long long threads = (long long)M * 32;
        spmm1norm_kernel<<<(int)((threads + 255) / 256), 256>>>(H0p, b0, H1, M);
    }

    // Layer 2 dense projection via WMMA split-fp16 (fp16 in, padded fp16 out)
    gemm2_wmma_kernel<<<(M + 127) / 128, 256, G2_SMEM>>>(H1, W1, Z2p, M);

    // SPMM2 + bias + log_softmax (warp/node, half2 gather, unroll 2)
    {
        long long threads = (long long)M * 32;
        spmm2lsm_kernel<<<(int)((threads + 255) / 256), 256>>>(Z2p, b1, out, M);
    }
}